// round 3
// baseline (speedup 1.0000x reference)
#include <cuda_runtime.h>
#include <math.h>

#define NS 50000
#define NA 50000
#define ES 1000000
#define EA 500000
#define HD 64

// Scratch (allocation-free rule): device globals, 16B-aligned for v4 atomics.
__device__ __align__(16) float g_sum_u[NS * HD];
__device__ __align__(16) float g_sum_x[NS * HD];
__device__ float g_deg[NS];

// Accurate tanh (~1e-7): MUFU ex2 + fast divide.
__device__ __forceinline__ float my_tanh(float v) {
    float ax = fabsf(v);
    float e  = __expf(-2.0f * ax);
    float t  = __fdividef(1.0f - e, 1.0f + e);
    return copysignf(t, v);
}

__device__ __forceinline__ void red_add4(float* p, float a, float b, float c, float d) {
    asm volatile("red.global.add.v4.f32 [%0], {%1,%2,%3,%4};"
                 :: "l"(p), "f"(a), "f"(b), "f"(c), "f"(d) : "memory");
}

// acc[0..15] += v * wrow[0..15]; wrow is smem, already offset to this slot's 16-col chunk.
__device__ __forceinline__ void accum16(float* acc, const float* wrow, float v) {
#pragma unroll
    for (int i = 0; i < 16; i += 4) {
        float4 w = *reinterpret_cast<const float4*>(wrow + i);
        acc[i + 0] += v * w.x;
        acc[i + 1] += v * w.y;
        acc[i + 2] += v * w.z;
        acc[i + 3] += v * w.w;
    }
}

// Weight layout in smem: row k occupies 80 floats, columns stored as slot*20 + i (i<16).
// Slots 0..3 then hit disjoint bank groups within each LDS phase.
#define WROW 80

// Copy [src_rows x 64] global weights into padded [dst_rows x WROW] smem layout.
// Rows >= src_rows are zero (input padding).
__device__ void cp_w_pad(float* dst, const float* __restrict__ src,
                         int src_rows, int dst_rows, int tid, int nt) {
    for (int idx = tid; idx < dst_rows * WROW; idx += nt) {
        int k = idx / WROW, c = idx % WROW;
        int slot = c / 20, i = c % 20;
        float v = 0.0f;
        if (i < 16 && k < src_rows) v = src[k * 64 + slot * 16 + i];
        dst[idx] = v;
    }
}
__device__ void cp_b(float* dst, const float* __restrict__ src, int tid, int nt) {
    for (int i = tid; i < 64; i += nt) dst[i] = src[i];
}

// Layers 2+3 for one slot (16 outputs). acc holds layer-1 preact on entry, final out on exit.
// zrow: this edge's activation-exchange row in smem (>= 64 floats usable, 16B aligned).
__device__ __forceinline__ void layers23_q(float* acc,
                                           const float* sW2, const float* sB2,
                                           const float* sW3, const float* sB3,
                                           float* zrow, int slot) {
    const float* w2s = sW2 + slot * 20;
    const float* w3s = sW3 + slot * 20;
    float4* zslot = reinterpret_cast<float4*>(zrow + slot * 16);

    // tanh(layer1) -> z
#pragma unroll
    for (int i = 0; i < 16; i += 4)
        zslot[i >> 2] = make_float4(my_tanh(acc[i]), my_tanh(acc[i + 1]),
                                    my_tanh(acc[i + 2]), my_tanh(acc[i + 3]));
    __syncwarp();
    // layer 2
#pragma unroll
    for (int i = 0; i < 16; i += 4) {
        float4 bv = *reinterpret_cast<const float4*>(sB2 + slot * 16 + i);
        acc[i] = bv.x; acc[i + 1] = bv.y; acc[i + 2] = bv.z; acc[i + 3] = bv.w;
    }
#pragma unroll 4
    for (int k4 = 0; k4 < 16; k4++) {
        float4 zv = *reinterpret_cast<const float4*>(zrow + k4 * 4);
        accum16(acc, w2s + (k4 * 4 + 0) * WROW, zv.x);
        accum16(acc, w2s + (k4 * 4 + 1) * WROW, zv.y);
        accum16(acc, w2s + (k4 * 4 + 2) * WROW, zv.z);
        accum16(acc, w2s + (k4 * 4 + 3) * WROW, zv.w);
    }
    __syncwarp();
    // tanh(layer2) -> z
#pragma unroll
    for (int i = 0; i < 16; i += 4)
        zslot[i >> 2] = make_float4(my_tanh(acc[i]), my_tanh(acc[i + 1]),
                                    my_tanh(acc[i + 2]), my_tanh(acc[i + 3]));
    __syncwarp();
    // layer 3
#pragma unroll
    for (int i = 0; i < 16; i += 4) {
        float4 bv = *reinterpret_cast<const float4*>(sB3 + slot * 16 + i);
        acc[i] = bv.x; acc[i + 1] = bv.y; acc[i + 2] = bv.z; acc[i + 3] = bv.w;
    }
#pragma unroll 4
    for (int k4 = 0; k4 < 16; k4++) {
        float4 zv = *reinterpret_cast<const float4*>(zrow + k4 * 4);
        accum16(acc, w3s + (k4 * 4 + 0) * WROW, zv.x);
        accum16(acc, w3s + (k4 * 4 + 1) * WROW, zv.y);
        accum16(acc, w3s + (k4 * 4 + 2) * WROW, zv.z);
        accum16(acc, w3s + (k4 * 4 + 3) * WROW, zv.w);
    }
    __syncwarp();  // z reads done before next tile's gather overwrites
}

// ---------------------------------------------------------------------------
__global__ void zero_kernel(void) {
    int i = blockIdx.x * blockDim.x + threadIdx.x;
    if (i < NS * HD) { g_sum_u[i] = 0.0f; g_sum_x[i] = 0.0f; }
    if (i < NS) g_deg[i] = 0.0f;
}

// ---------------------------------------------------------------------------
// s2s: in = [ps_src(2), ps_dst(2), dis(1), x[src](8), h[src](64)] = 77 -> pad 80
// 256 threads = 64 edges/tile, 4 threads per edge. z row stride 100 (== 4 mod 32).
#define S2S_ZSTRIDE 100
#define S2S_W1R 80
// smem floats: W1 80*80=6400, B1 64, W2 5120, B2 64, W3 5120, B3 64, Z 64*100=6400
#define S2S_SMF (6400 + 64 + 5120 + 64 + 5120 + 64 + 6400)

__global__ void __launch_bounds__(256) s2s_kernel(
    const float* __restrict__ pos_state, const float* __restrict__ xin,
    const float* __restrict__ h,
    const int* __restrict__ esrc, const int* __restrict__ edst,
    const float* __restrict__ edis,
    const float* __restrict__ W1, const float* __restrict__ B1,
    const float* __restrict__ W2, const float* __restrict__ B2,
    const float* __restrict__ W3, const float* __restrict__ B3) {
    extern __shared__ float sm[];
    float* sW1 = sm;                       // 6400
    float* sB1 = sW1 + 6400;               // 64
    float* sW2 = sB1 + 64;                 // 5120
    float* sB2 = sW2 + 5120;               // 64
    float* sW3 = sB2 + 64;                 // 5120
    float* sB3 = sW3 + 5120;               // 64
    float* zbase = sB3 + 64;               // 6400
    int tid = threadIdx.x, nt = blockDim.x;
    cp_w_pad(sW1, W1, 77, S2S_W1R, tid, nt);
    cp_b(sB1, B1, tid, nt);
    cp_w_pad(sW2, W2, 64, 64, tid, nt);
    cp_b(sB2, B2, tid, nt);
    cp_w_pad(sW3, W3, 64, 64, tid, nt);
    cp_b(sB3, B3, tid, nt);
    for (int i = tid; i < 64 * S2S_ZSTRIDE; i += nt) zbase[i] = 0.0f;
    __syncthreads();

    int slot = tid & 3;
    float* zrow = zbase + (tid >> 2) * S2S_ZSTRIDE;
    const float* w1s = sW1 + slot * 20;

    for (int base = blockIdx.x * 64; base < ES; base += gridDim.x * 64) {
        int e = base + (tid >> 2);
        bool act = e < ES;
        int ec = act ? e : (ES - 1);
        int s = esrc[ec], d = edst[ec];

        // gather: h quarter (aligned), slot0 scalars, slot1 x
        const float4* h4 = reinterpret_cast<const float4*>(h + (size_t)s * 64);
#pragma unroll
        for (int i = 0; i < 4; i++) {
            float4 v = h4[slot * 4 + i];
            int b = 13 + slot * 16 + i * 4;
            zrow[b] = v.x; zrow[b + 1] = v.y; zrow[b + 2] = v.z; zrow[b + 3] = v.w;
        }
        if (slot == 0) {
            float2 ps_ = *reinterpret_cast<const float2*>(pos_state + 2 * (size_t)s);
            float2 pd_ = *reinterpret_cast<const float2*>(pos_state + 2 * (size_t)d);
            zrow[0] = ps_.x; zrow[1] = ps_.y; zrow[2] = pd_.x; zrow[3] = pd_.y;
            zrow[4] = edis[ec];
        } else if (slot == 1) {
            const float4* x4 = reinterpret_cast<const float4*>(xin + 8 * (size_t)s);
            float4 a = x4[0], b4 = x4[1];
            zrow[5] = a.x; zrow[6] = a.y; zrow[7] = a.z; zrow[8] = a.w;
            zrow[9] = b4.x; zrow[10] = b4.y; zrow[11] = b4.z; zrow[12] = b4.w;
        }
        __syncwarp();

        float acc[16];
#pragma unroll
        for (int i = 0; i < 16; i += 4) {
            float4 bv = *reinterpret_cast<const float4*>(sB1 + slot * 16 + i);
            acc[i] = bv.x; acc[i + 1] = bv.y; acc[i + 2] = bv.z; acc[i + 3] = bv.w;
        }
#pragma unroll 4
        for (int k4 = 0; k4 < S2S_W1R / 4; k4++) {
            float4 zv = *reinterpret_cast<const float4*>(zrow + k4 * 4);
            accum16(acc, w1s + (k4 * 4 + 0) * WROW, zv.x);
            accum16(acc, w1s + (k4 * 4 + 1) * WROW, zv.y);
            accum16(acc, w1s + (k4 * 4 + 2) * WROW, zv.z);
            accum16(acc, w1s + (k4 * 4 + 3) * WROW, zv.w);
        }
        __syncwarp();
        layers23_q(acc, sW2, sB2, sW3, sB3, zrow, slot);

        if (act) {
            float* outp = g_sum_x + (size_t)d * 64 + slot * 16;
            red_add4(outp + 0,  acc[0],  acc[1],  acc[2],  acc[3]);
            red_add4(outp + 4,  acc[4],  acc[5],  acc[6],  acc[7]);
            red_add4(outp + 8,  acc[8],  acc[9],  acc[10], acc[11]);
            red_add4(outp + 12, acc[12], acc[13], acc[14], acc[15]);
            if (slot == 0) atomicAdd(g_deg + d, 1.0f);
        }
    }
}

// ---------------------------------------------------------------------------
// a2s: in = [pa_src(2), ps_dst(2), dis(1), u[src](8)] = 13 -> pad 16. z stride 68.
#define A2S_ZSTRIDE 68
#define A2S_W1R 16
// smem floats: W1 16*80=1280, B1 64, W2 5120, B2 64, W3 5120, B3 64, Z 64*68=4352
#define A2S_SMF (1280 + 64 + 5120 + 64 + 5120 + 64 + 4352)

__global__ void __launch_bounds__(256) a2s_kernel(
    const float* __restrict__ pos_state, const float* __restrict__ pos_action,
    const float* __restrict__ u,
    const int* __restrict__ esrc, const int* __restrict__ edst,
    const float* __restrict__ edis,
    const float* __restrict__ W1, const float* __restrict__ B1,
    const float* __restrict__ W2, const float* __restrict__ B2,
    const float* __restrict__ W3, const float* __restrict__ B3) {
    extern __shared__ float sm[];
    float* sW1 = sm;                       // 1280
    float* sB1 = sW1 + 1280;
    float* sW2 = sB1 + 64;
    float* sB2 = sW2 + 5120;
    float* sW3 = sB2 + 64;
    float* sB3 = sW3 + 5120;
    float* zbase = sB3 + 64;               // 4352
    int tid = threadIdx.x, nt = blockDim.x;
    cp_w_pad(sW1, W1, 13, A2S_W1R, tid, nt);
    cp_b(sB1, B1, tid, nt);
    cp_w_pad(sW2, W2, 64, 64, tid, nt);
    cp_b(sB2, B2, tid, nt);
    cp_w_pad(sW3, W3, 64, 64, tid, nt);
    cp_b(sB3, B3, tid, nt);
    for (int i = tid; i < 64 * A2S_ZSTRIDE; i += nt) zbase[i] = 0.0f;
    __syncthreads();

    int slot = tid & 3;
    float* zrow = zbase + (tid >> 2) * A2S_ZSTRIDE;
    const float* w1s = sW1 + slot * 20;

    for (int base = blockIdx.x * 64; base < EA; base += gridDim.x * 64) {
        int e = base + (tid >> 2);
        bool act = e < EA;
        int ec = act ? e : (EA - 1);
        int s = esrc[ec], d = edst[ec];

        if (slot == 0) {
            float2 pa_ = *reinterpret_cast<const float2*>(pos_action + 2 * (size_t)s);
            float2 pd_ = *reinterpret_cast<const float2*>(pos_state + 2 * (size_t)d);
            zrow[0] = pa_.x; zrow[1] = pa_.y; zrow[2] = pd_.x; zrow[3] = pd_.y;
            zrow[4] = edis[ec];
        } else if (slot == 1) {
            const float4* u4 = reinterpret_cast<const float4*>(u + 8 * (size_t)s);
            float4 a = u4[0], b4 = u4[1];
            zrow[5] = a.x; zrow[6] = a.y; zrow[7] = a.z; zrow[8] = a.w;
            zrow[9] = b4.x; zrow[10] = b4.y; zrow[11] = b4.z; zrow[12] = b4.w;
        }
        __syncwarp();

        float acc[16];
#pragma unroll
        for (int i = 0; i < 16; i += 4) {
            float4 bv = *reinterpret_cast<const float4*>(sB1 + slot * 16 + i);
            acc[i] = bv.x; acc[i + 1] = bv.y; acc[i + 2] = bv.z; acc[i + 3] = bv.w;
        }
#pragma unroll
        for (int k4 = 0; k4 < A2S_W1R / 4; k4++) {
            float4 zv = *reinterpret_cast<const float4*>(zrow + k4 * 4);
            accum16(acc, w1s + (k4 * 4 + 0) * WROW, zv.x);
            accum16(acc, w1s + (k4 * 4 + 1) * WROW, zv.y);
            accum16(acc, w1s + (k4 * 4 + 2) * WROW, zv.z);
            accum16(acc, w1s + (k4 * 4 + 3) * WROW, zv.w);
        }
        __syncwarp();
        layers23_q(acc, sW2, sB2, sW3, sB3, zrow, slot);

        if (act) {
            float* outp = g_sum_u + (size_t)d * 64 + slot * 16;
            red_add4(outp + 0,  acc[0],  acc[1],  acc[2],  acc[3]);
            red_add4(outp + 4,  acc[4],  acc[5],  acc[6],  acc[7]);
            red_add4(outp + 8,  acc[8],  acc[9],  acc[10], acc[11]);
            red_add4(outp + 12, acc[12], acc[13], acc[14], acc[15]);
        }
    }
}

// ---------------------------------------------------------------------------
// upd: in = [pos(2), h(64), sum_u(64), mean_x(64), x(8)] = 202. Layer-1 inputs
// streamed from global (4 slots read same addresses -> coalesced broadcast).
#define UPD_ZSTRIDE 68
// smem floats: W1 202*80=16160, B1 64, W2 5120, B2 64, W3 5120, B3 64, Z 4352
#define UPD_SMF (16160 + 64 + 5120 + 64 + 5120 + 64 + 4352)

__global__ void __launch_bounds__(256) upd_kernel(
    const float* __restrict__ pos_state, const float* __restrict__ h,
    const float* __restrict__ xin,
    const float* __restrict__ W1, const float* __restrict__ B1,
    const float* __restrict__ W2, const float* __restrict__ B2,
    const float* __restrict__ W3, const float* __restrict__ B3,
    float* __restrict__ out) {
    extern __shared__ float sm[];
    float* sW1 = sm;                       // 16160
    float* sB1 = sW1 + 16160;
    float* sW2 = sB1 + 64;
    float* sB2 = sW2 + 5120;
    float* sW3 = sB2 + 64;
    float* sB3 = sW3 + 5120;
    float* zbase = sB3 + 64;
    int tid = threadIdx.x, nt = blockDim.x;
    cp_w_pad(sW1, W1, 202, 202, tid, nt);
    cp_b(sB1, B1, tid, nt);
    cp_w_pad(sW2, W2, 64, 64, tid, nt);
    cp_b(sB2, B2, tid, nt);
    cp_w_pad(sW3, W3, 64, 64, tid, nt);
    cp_b(sB3, B3, tid, nt);
    __syncthreads();

    int slot = tid & 3;
    float* zrow = zbase + (tid >> 2) * UPD_ZSTRIDE;
    const float* w1s = sW1 + slot * 20;

    for (int base = blockIdx.x * 64; base < NS; base += gridDim.x * 64) {
        int n = base + (tid >> 2);
        bool act = n < NS;
        int nc = act ? n : (NS - 1);

        float acc[16];
#pragma unroll
        for (int i = 0; i < 16; i += 4) {
            float4 bv = *reinterpret_cast<const float4*>(sB1 + slot * 16 + i);
            acc[i] = bv.x; acc[i + 1] = bv.y; acc[i + 2] = bv.z; acc[i + 3] = bv.w;
        }
        float2 ps_ = *reinterpret_cast<const float2*>(pos_state + 2 * (size_t)nc);
        accum16(acc, w1s + 0 * WROW, ps_.x);
        accum16(acc, w1s + 1 * WROW, ps_.y);
        const float4* h4 = reinterpret_cast<const float4*>(h + 64 * (size_t)nc);
#pragma unroll 4
        for (int k2 = 0; k2 < 16; k2++) {
            float4 v = h4[k2];
            accum16(acc, w1s + (2 + 4 * k2 + 0) * WROW, v.x);
            accum16(acc, w1s + (2 + 4 * k2 + 1) * WROW, v.y);
            accum16(acc, w1s + (2 + 4 * k2 + 2) * WROW, v.z);
            accum16(acc, w1s + (2 + 4 * k2 + 3) * WROW, v.w);
        }
        const float4* su4 = reinterpret_cast<const float4*>(g_sum_u + 64 * (size_t)nc);
#pragma unroll 4
        for (int k2 = 0; k2 < 16; k2++) {
            float4 v = su4[k2];
            accum16(acc, w1s + (66 + 4 * k2 + 0) * WROW, v.x);
            accum16(acc, w1s + (66 + 4 * k2 + 1) * WROW, v.y);
            accum16(acc, w1s + (66 + 4 * k2 + 2) * WROW, v.z);
            accum16(acc, w1s + (66 + 4 * k2 + 3) * WROW, v.w);
        }
        float dg = g_deg[nc];
        float inv = __fdividef(1.0f, fmaxf(dg, 1.0f));
        const float4* sx4 = reinterpret_cast<const float4*>(g_sum_x + 64 * (size_t)nc);
#pragma unroll 4
        for (int k2 = 0; k2 < 16; k2++) {
            float4 v = sx4[k2];
            accum16(acc, w1s + (130 + 4 * k2 + 0) * WROW, v.x * inv);
            accum16(acc, w1s + (130 + 4 * k2 + 1) * WROW, v.y * inv);
            accum16(acc, w1s + (130 + 4 * k2 + 2) * WROW, v.z * inv);
            accum16(acc, w1s + (130 + 4 * k2 + 3) * WROW, v.w * inv);
        }
        const float4* x4 = reinterpret_cast<const float4*>(xin + 8 * (size_t)nc);
#pragma unroll
        for (int k2 = 0; k2 < 2; k2++) {
            float4 v = x4[k2];
            accum16(acc, w1s + (194 + 4 * k2 + 0) * WROW, v.x);
            accum16(acc, w1s + (194 + 4 * k2 + 1) * WROW, v.y);
            accum16(acc, w1s + (194 + 4 * k2 + 2) * WROW, v.z);
            accum16(acc, w1s + (194 + 4 * k2 + 3) * WROW, v.w);
        }
        layers23_q(acc, sW2, sB2, sW3, sB3, zrow, slot);

        if (act) {
            float4* o4 = reinterpret_cast<float4*>(out + 64 * (size_t)n + slot * 16);
#pragma unroll
            for (int j = 0; j < 4; j++)
                o4[j] = make_float4(acc[4 * j], acc[4 * j + 1], acc[4 * j + 2], acc[4 * j + 3]);
        }
    }
}

// ---------------------------------------------------------------------------
extern "C" void kernel_launch(void* const* d_in, const int* in_sizes, int n_in,
                              void* d_out, int out_size) {
    const float* pos_state  = (const float*)d_in[0];
    const float* pos_action = (const float*)d_in[1];
    const float* h          = (const float*)d_in[2];
    const float* x          = (const float*)d_in[3];
    const float* u          = (const float*)d_in[4];
    const int*   a2s_src    = (const int*)d_in[5];
    const int*   a2s_dst    = (const int*)d_in[6];
    const float* a2s_dis    = (const float*)d_in[7];
    const int*   s2s_src    = (const int*)d_in[8];
    const int*   s2s_dst    = (const int*)d_in[9];
    const float* s2s_dis    = (const float*)d_in[10];
    const float* u2h_w1 = (const float*)d_in[11];
    const float* u2h_b1 = (const float*)d_in[12];
    const float* u2h_w2 = (const float*)d_in[13];
    const float* u2h_b2 = (const float*)d_in[14];
    const float* u2h_w3 = (const float*)d_in[15];
    const float* u2h_b3 = (const float*)d_in[16];
    const float* x2h_w1 = (const float*)d_in[17];
    const float* x2h_b1 = (const float*)d_in[18];
    const float* x2h_w2 = (const float*)d_in[19];
    const float* x2h_b2 = (const float*)d_in[20];
    const float* x2h_w3 = (const float*)d_in[21];
    const float* x2h_b3 = (const float*)d_in[22];
    const float* upd_w1 = (const float*)d_in[23];
    const float* upd_b1 = (const float*)d_in[24];
    const float* upd_w2 = (const float*)d_in[25];
    const float* upd_b2 = (const float*)d_in[26];
    const float* upd_w3 = (const float*)d_in[27];
    const float* upd_b3 = (const float*)d_in[28];
    float* out = (float*)d_out;

    const int S2S_SMEM = S2S_SMF * 4;
    const int A2S_SMEM = A2S_SMF * 4;
    const int UPD_SMEM = UPD_SMF * 4;
    cudaFuncSetAttribute(s2s_kernel, cudaFuncAttributeMaxDynamicSharedMemorySize, S2S_SMEM);
    cudaFuncSetAttribute(a2s_kernel, cudaFuncAttributeMaxDynamicSharedMemorySize, A2S_SMEM);
    cudaFuncSetAttribute(upd_kernel, cudaFuncAttributeMaxDynamicSharedMemorySize, UPD_SMEM);

    zero_kernel<<<(NS * HD + 255) / 256, 256>>>();

    a2s_kernel<<<444, 256, A2S_SMEM>>>(
        pos_state, pos_action, u, a2s_src, a2s_dst, a2s_dis,
        u2h_w1, u2h_b1, u2h_w2, u2h_b2, u2h_w3, u2h_b3);

    s2s_kernel<<<296, 256, S2S_SMEM>>>(
        pos_state, x, h, s2s_src, s2s_dst, s2s_dis,
        x2h_w1, x2h_b1, x2h_w2, x2h_b2, x2h_w3, x2h_b3);

    upd_kernel<<<148, 256, UPD_SMEM>>>(
        pos_state, h, x,
        upd_w1, upd_b1, upd_w2, upd_b2, upd_w3, upd_b3,
        out);
}